// round 13
// baseline (speedup 1.0000x reference)
#include <cuda_runtime.h>
#include <cuda_bf16.h>
#include <cuda_fp16.h>
#include <stdint.h>

#define NN 100000
#define EE 1600000
#define CC 128
#define HH 256
#define BB 5000          // NN / 20
#define NPAD 100096      // 1564 * 64
#define MAXDEG 64

// ---------------- scratch (device globals; no allocation allowed) ------------
__device__ __align__(16) int    g_cnt [NN];
__device__ __align__(16) int    g_adj [(long long)NN * MAXDEG];
__device__ __align__(16) float  g_dinv[NN];
__device__ __align__(16) __half g_cwTh[CC * CC];     // conv_w^T (half, [n][k])
__device__ __align__(16) __half g_w1h [HH * CC];     // lin1_w (half)
__device__ __align__(16) __half g_w2h [HH * HH];     // lin2_w (half)
__device__ __align__(16) __half g_xwh [NPAD * CC];   // x @ conv_w (fp16)
__device__ __align__(16) __half g_acch[NPAD * CC];   // h (fp16), padding stays 0
__device__ __align__(16) __half g_h1h [NPAD * HH];   // relu(h@W1^T+b1) (fp16)

// ---------------- graph-side kernels -----------------------------------------
__global__ void zero_cnt_kernel() {
    int i = blockIdx.x * blockDim.x + threadIdx.x;
    if (i < NN) g_cnt[i] = 0;
}

// 4 edges per thread: 4 independent atomic chains in flight
__global__ void build_adj_kernel(const int* __restrict__ ei) {
    int base = (blockIdx.x * blockDim.x + threadIdx.x) * 4;
    if (base >= EE) return;
    const int4 s4 = *(const int4*)&ei[base];
    const int4 d4 = *(const int4*)&ei[EE + base];
    int ss[4] = {s4.x, s4.y, s4.z, s4.w};
    int dd[4] = {d4.x, d4.y, d4.z, d4.w};
    int slot[4];
#pragma unroll
    for (int u = 0; u < 4; u++)
        slot[u] = atomicAdd(&g_cnt[dd[u]], 1);
#pragma unroll
    for (int u = 0; u < 4; u++)
        if (slot[u] < MAXDEG) g_adj[(long long)dd[u] * MAXDEG + slot[u]] = ss[u];
}

__global__ void dinv_kernel() {
    int i = blockIdx.x * blockDim.x + threadIdx.x;
    if (i < NN) g_dinv[i] = rsqrtf((float)g_cnt[i] + 1.0f);
}

// ---------------- prep: convert weights + init out ---------------------------
__global__ void prep_kernel(const float* __restrict__ cw,
                            const float* __restrict__ w1,
                            const float* __restrict__ w2,
                            const float* __restrict__ b3,
                            float* __restrict__ outp) {
    int i = blockIdx.x * blockDim.x + threadIdx.x;   // 114688
    if (i < BB) outp[i] = b3[0];
    if (i < CC * CC) {
        int k = i >> 7, n = i & 127;
        g_cwTh[n * CC + k] = __float2half_rn(cw[k * CC + n]);
    } else if (i < CC * CC + HH * CC) {
        int j = i - CC * CC;
        g_w1h[j] = __float2half_rn(w1[j]);
    } else if (i < CC * CC + HH * CC + HH * HH) {
        int j = i - CC * CC - HH * CC;
        g_w2h[j] = __float2half_rn(w2[j]);
    }
}

// ---------------- helpers ----------------------------------------------------
__device__ __forceinline__ uint32_t packh2(float a, float b) {
    __half2 h = __floats2half2_rn(a, b);
    return *(uint32_t*)&h;
}

__device__ __forceinline__ void ldsm4(uint32_t& r0, uint32_t& r1,
                                      uint32_t& r2, uint32_t& r3, uint32_t addr) {
    asm volatile("ldmatrix.sync.aligned.m8n8.x4.shared.b16 {%0,%1,%2,%3}, [%4];"
                 : "=r"(r0), "=r"(r1), "=r"(r2), "=r"(r3) : "r"(addr));
}

__device__ __forceinline__ void cpasync16(uint32_t dst, const void* src) {
    asm volatile("cp.async.cg.shared.global [%0], [%1], 16;"
                 :: "r"(dst), "l"(src) : "memory");
}

#define MMA_F16(D, AV, BV)                                                      \
    asm volatile(                                                               \
        "mma.sync.aligned.m16n8k16.row.col.f32.f16.f16.f32 "                    \
        "{%0,%1,%2,%3}, {%4,%5,%6,%7}, {%8,%9}, {%0,%1,%2,%3};"                 \
        : "+f"((D)[0]), "+f"((D)[1]), "+f"((D)[2]), "+f"((D)[3])                \
        : "r"((AV).x), "r"((AV).y), "r"((AV).z), "r"((AV).w),                   \
          "r"((BV).x), "r"((BV).y))

// ---------------- fp16 tensor-core GEMM: M-tile 64, ldmatrix + cp.async ------
// C[row, n] = sum_k A[row, k] * B[n, k]   (B half, torch [n][k] layout)
// Block tile 64(M) x 128(N), KT=32; 8 warps: 4(M, 16 rows each) x 2(N, 64 each).
// SMEM row-major tiles, 32 halves (4x16B units)/row; XOR swizzle on 16B units
// pu = u ^ ((r>>1)&3). Fills via cp.async; 2-stage double buffering.
// EPI 0: outh[row*CC + col] = (half)c              (conv; clamp A row reads)
// EPI 1: outh[row*HH + col] = (half)relu(c + bias[col])
// EPI 2: out0[row/20] += sum_n relu(c + bias[n]) * w3[n]   (row < arows)
template<int KDIM, int EPI, bool AHALF>
__global__ void __launch_bounds__(256, 3) hgemm_kernel(
    const void* __restrict__ Aptr,
    const __half* __restrict__ W,
    const float* __restrict__ bias,
    const float* __restrict__ w3,
    float* __restrict__ out0,
    __half* __restrict__ outh,
    int arows)
{
    __shared__ __align__(16) __half sA[2][64 * 32];    // 4 KB / stage
    __shared__ __align__(16) __half sB[2][128 * 32];   // 8 KB / stage

    const int tid = threadIdx.x;
    const int lane = tid & 31;
    const int wid = tid >> 5;
    const int wm = wid & 3;          // warp m-tile (16 rows)
    const int wn = wid >> 2;         // warp n-half (64 cols)
    const int gid = lane >> 2;
    const int tidg = lane & 3;
    const int row0 = blockIdx.x * 64;
    const int jb = blockIdx.y * 128;

    float d[8][4];
#pragma unroll
    for (int j = 0; j < 8; j++)
#pragma unroll
        for (int r = 0; r < 4; r++) d[j][r] = 0.0f;

    const int laneRowA = lane & 15;
    const int laneUHA  = lane >> 4;
    const int laneRowB = (lane & 7) + ((lane >> 4) << 3);
    const int laneUHB  = (lane >> 3) & 1;

    auto fillA = [&](int st, int kt0) {
        // 64 rows x 32 k = 256 16B units, 1 per thread
        int r = tid >> 2, u = tid & 3;
        int grow = row0 + r;
        if (EPI == 0 && grow >= arows) grow = 0;   // clamp reads of x
        int pu = u ^ ((r >> 1) & 3);
        if (AHALF) {
            const void* src = &((const __half*)Aptr)[(long long)grow * KDIM + kt0 + u * 8];
            uint32_t dst = (uint32_t)__cvta_generic_to_shared(&sA[st][r * 32 + pu * 8]);
            cpasync16(dst, src);
        } else {
            const float* Af = (const float*)Aptr;
            const float4 v0 = *(const float4*)&Af[(long long)grow * KDIM + kt0 + u * 8];
            const float4 v1 = *(const float4*)&Af[(long long)grow * KDIM + kt0 + u * 8 + 4];
            uint4 val;
            val.x = packh2(v0.x, v0.y); val.y = packh2(v0.z, v0.w);
            val.z = packh2(v1.x, v1.y); val.w = packh2(v1.z, v1.w);
            *(uint4*)&sA[st][r * 32 + pu * 8] = val;
        }
    };
    auto fillB = [&](int st, int kt0) {
#pragma unroll
        for (int t = 0; t < 2; t++) {
            int idx = tid + t * 256;
            int r = idx >> 2, u = idx & 3;
            int pu = u ^ ((r >> 1) & 3);
            const void* src = &W[(long long)(jb + r) * KDIM + kt0 + u * 8];
            uint32_t dst = (uint32_t)__cvta_generic_to_shared(&sB[st][r * 32 + pu * 8]);
            cpasync16(dst, src);
        }
    };
    auto compute = [&](int st) {
        const uint32_t baseA = (uint32_t)__cvta_generic_to_shared(&sA[st][0]);
        const uint32_t baseB = (uint32_t)__cvta_generic_to_shared(&sB[st][0]);
#pragma unroll
        for (int s = 0; s < 2; s++) {
            uint4 av;
            uint2 bv[8];
            {
                int row = wm * 16 + laneRowA;
                int u = s * 2 + laneUHA;
                uint32_t addr = baseA + (uint32_t)((row * 4 + (u ^ ((row >> 1) & 3))) << 4);
                ldsm4(av.x, av.y, av.z, av.w, addr);
            }
#pragma unroll
            for (int jj = 0; jj < 4; jj++) {
                int row = wn * 64 + jj * 16 + laneRowB;
                int u = s * 2 + laneUHB;
                uint32_t addr = baseB + (uint32_t)((row * 4 + (u ^ ((row >> 1) & 3))) << 4);
                ldsm4(bv[jj * 2].x, bv[jj * 2].y, bv[jj * 2 + 1].x, bv[jj * 2 + 1].y, addr);
            }
#pragma unroll
            for (int j = 0; j < 8; j++)
                MMA_F16(d[j], av, bv[j]);
        }
    };

    constexpr int NT = KDIM / 32;
    fillA(0, 0);
    fillB(0, 0);
    asm volatile("cp.async.commit_group;");
    int buf = 0;
#pragma unroll
    for (int t = 0; t < NT; t++) {
        if (t + 1 < NT) {
            fillA(buf ^ 1, (t + 1) * 32);
            fillB(buf ^ 1, (t + 1) * 32);
            asm volatile("cp.async.commit_group;");
            asm volatile("cp.async.wait_group 1;");
        } else {
            asm volatile("cp.async.wait_group 0;");
        }
        __syncthreads();
        compute(buf);
        __syncthreads();
        buf ^= 1;
    }

    const int rbase = row0 + wm * 16 + gid;
    if (EPI == 0) {
#pragma unroll
        for (int j = 0; j < 8; j++) {
            const int c = jb + (wn * 8 + j) * 8 + tidg * 2;
            *(__half2*)&outh[(long long)rbase * CC + c] =
                __floats2half2_rn(d[j][0], d[j][1]);
            *(__half2*)&outh[(long long)(rbase + 8) * CC + c] =
                __floats2half2_rn(d[j][2], d[j][3]);
        }
    } else if (EPI == 1) {
#pragma unroll
        for (int j = 0; j < 8; j++) {
            const int c = jb + (wn * 8 + j) * 8 + tidg * 2;
            const float bb0 = bias[c], bb1 = bias[c + 1];
            *(__half2*)&outh[(long long)rbase * HH + c] =
                __floats2half2_rn(fmaxf(d[j][0] + bb0, 0.0f),
                                  fmaxf(d[j][1] + bb1, 0.0f));
            *(__half2*)&outh[(long long)(rbase + 8) * HH + c] =
                __floats2half2_rn(fmaxf(d[j][2] + bb0, 0.0f),
                                  fmaxf(d[j][3] + bb1, 0.0f));
        }
    } else {
        float v0 = 0.0f, v1 = 0.0f;
#pragma unroll
        for (int j = 0; j < 8; j++) {
            const int c = jb + (wn * 8 + j) * 8 + tidg * 2;
            const float bb0 = bias[c], bb1 = bias[c + 1];
            const float w30 = w3[c], w31 = w3[c + 1];
            v0 += fmaxf(d[j][0] + bb0, 0.0f) * w30
                + fmaxf(d[j][1] + bb1, 0.0f) * w31;
            v1 += fmaxf(d[j][2] + bb0, 0.0f) * w30
                + fmaxf(d[j][3] + bb1, 0.0f) * w31;
        }
        v0 += __shfl_xor_sync(0xffffffffu, v0, 1);
        v0 += __shfl_xor_sync(0xffffffffu, v0, 2);
        v1 += __shfl_xor_sync(0xffffffffu, v1, 1);
        v1 += __shfl_xor_sync(0xffffffffu, v1, 2);
        if (tidg == 0) {
            if (rbase < arows)     atomicAdd(&out0[rbase / 20], v0);
            if (rbase + 8 < arows) atomicAdd(&out0[(rbase + 8) / 20], v1);
        }
    }
}

// ---------------- pull aggregation + fused conv epilogue ---------------------
__device__ __forceinline__ float4 load_xw_row(int node, int lane) {
    const uint2 u = *(const uint2*)(g_xwh + (long long)node * CC + lane * 4);
    __half2 a = *(const __half2*)&u.x;
    __half2 b = *(const __half2*)&u.y;
    float2 fa = __half22float2(a), fb = __half22float2(b);
    return make_float4(fa.x, fa.y, fb.x, fb.y);
}

__global__ void __launch_bounds__(256) aggregate_kernel(
    const float* __restrict__ x, const float* __restrict__ cb)
{
    const int wid = threadIdx.x >> 5;
    const int lane = threadIdx.x & 31;
    const int d = blockIdx.x * 8 + wid;
    if (d >= NN) return;

    int cnt = g_cnt[d];
    if (cnt > MAXDEG) cnt = MAXDEG;
    const float dv = g_dinv[d];

    const int* adj = &g_adj[(long long)d * MAXDEG];
    int s0 = (lane < cnt) ? adj[lane] : 0;
    int s1 = (lane + 32 < cnt) ? adj[lane + 32] : 0;
    float n0 = (lane < cnt) ? g_dinv[s0] * dv : 0.0f;
    float n1 = (lane + 32 < cnt) ? g_dinv[s1] * dv : 0.0f;

    float4 acc = load_xw_row(d, lane);
    const float sl = dv * dv;
    acc.x *= sl; acc.y *= sl; acc.z *= sl; acc.w *= sl;

    int i = 0;
    for (; i + 4 <= cnt; i += 4) {
#pragma unroll
        for (int u = 0; u < 4; u++) {
            int e = i + u;
            int src = __shfl_sync(0xffffffffu, (e < 32) ? s0 : s1, e & 31);
            float nm = __shfl_sync(0xffffffffu, (e < 32) ? n0 : n1, e & 31);
            float4 v = load_xw_row(src, lane);
            acc.x += v.x * nm; acc.y += v.y * nm;
            acc.z += v.z * nm; acc.w += v.w * nm;
        }
    }
    for (; i < cnt; i++) {
        int src = __shfl_sync(0xffffffffu, (i < 32) ? s0 : s1, i & 31);
        float nm = __shfl_sync(0xffffffffu, (i < 32) ? n0 : n1, i & 31);
        float4 v = load_xw_row(src, lane);
        acc.x += v.x * nm; acc.y += v.y * nm;
        acc.z += v.z * nm; acc.w += v.w * nm;
    }

    float4 bb = ((const float4*)cb)[lane];
    float4 xv = ((const float4*)(x + (long long)d * CC))[lane];
    uint2 st;
    st.x = packh2(fmaxf(acc.x + bb.x, 0.0f) + xv.x,
                  fmaxf(acc.y + bb.y, 0.0f) + xv.y);
    st.y = packh2(fmaxf(acc.z + bb.z, 0.0f) + xv.z,
                  fmaxf(acc.w + bb.w, 0.0f) + xv.w);
    *(uint2*)(g_acch + (long long)d * CC + lane * 4) = st;
}

// ---------------- launch -----------------------------------------------------
extern "C" void kernel_launch(void* const* d_in, const int* in_sizes, int n_in,
                              void* d_out, int out_size) {
    const float* x   = (const float*)d_in[0];
    const int*   ei  = (const int*)d_in[1];
    const float* cw  = (const float*)d_in[2];
    const float* cb  = (const float*)d_in[3];
    const float* w1  = (const float*)d_in[4];
    const float* b1  = (const float*)d_in[5];
    const float* w2  = (const float*)d_in[6];
    const float* b2  = (const float*)d_in[7];
    const float* w3  = (const float*)d_in[8];
    const float* b3  = (const float*)d_in[9];
    float* outp = (float*)d_out;

    __half* p_cwTh; cudaGetSymbolAddress((void**)&p_cwTh, g_cwTh);
    __half* p_w1h;  cudaGetSymbolAddress((void**)&p_w1h,  g_w1h);
    __half* p_w2h;  cudaGetSymbolAddress((void**)&p_w2h,  g_w2h);
    __half* p_xwh;  cudaGetSymbolAddress((void**)&p_xwh,  g_xwh);
    __half* p_acch; cudaGetSymbolAddress((void**)&p_acch, g_acch);
    __half* p_h1h;  cudaGetSymbolAddress((void**)&p_h1h,  g_h1h);

    // one-time host resources (created on the uncaptured correctness call)
    static cudaStream_t s_side = nullptr;
    static cudaEvent_t evFork = nullptr, evJoin = nullptr;
    if (!s_side) {
        cudaStreamCreateWithFlags(&s_side, cudaStreamNonBlocking);
        cudaEventCreateWithFlags(&evFork, cudaEventDisableTiming);
        cudaEventCreateWithFlags(&evJoin, cudaEventDisableTiming);
    }

    // fork: side stream runs prep + conv GEMM while main stream builds the graph
    cudaEventRecord(evFork, 0);
    cudaStreamWaitEvent(s_side, evFork, 0);

    prep_kernel<<<(CC * CC + HH * CC + HH * HH + 255) / 256, 256, 0, s_side>>>(
        cw, w1, w2, b3, outp);
    hgemm_kernel<128, 0, false><<<dim3(NPAD / 64, 1), 256, 0, s_side>>>(
        x, p_cwTh, nullptr, nullptr, nullptr, p_xwh, NN);
    cudaEventRecord(evJoin, s_side);

    zero_cnt_kernel<<<(NN + 255) / 256, 256>>>();
    build_adj_kernel<<<(EE / 4 + 255) / 256, 256>>>(ei);
    dinv_kernel<<<(NN + 255) / 256, 256>>>();

    // join: aggregation needs g_xwh (side) + g_cnt/g_dinv (main)
    cudaStreamWaitEvent(0, evJoin, 0);

    aggregate_kernel<<<(NN + 7) / 8, 256>>>(x, cb);

    // mlp1: g_h1h = relu(h @ W1^T + b1)
    hgemm_kernel<128, 1, true><<<dim3(NPAD / 64, 2), 256>>>(
        p_acch, p_w1h, b1, nullptr, nullptr, p_h1h, NN);

    // mlp2 + fused sum/lin3
    hgemm_kernel<256, 2, true><<<dim3(NPAD / 64, 2), 256>>>(
        p_h1h, p_w2h, b2, w3, outp, nullptr, NN);
}

// round 14
// speedup vs baseline: 1.1208x; 1.1208x over previous
#include <cuda_runtime.h>
#include <cuda_bf16.h>
#include <cuda_fp16.h>
#include <stdint.h>

#define NN 100000
#define EE 1600000
#define CC 128
#define HH 256
#define BB 5000          // NN / 20
#define NPAD 100096      // 782 * 128
#define MAXDEG 64

// ---------------- scratch (device globals; no allocation allowed) ------------
__device__ __align__(16) int    g_cnt [NN];
__device__ __align__(16) int    g_adj [(long long)NN * MAXDEG];
__device__ __align__(16) float  g_dinv[NN];
__device__ __align__(16) __half g_cwTh[CC * CC];     // conv_w^T (half, [n][k])
__device__ __align__(16) __half g_w1h [HH * CC];     // lin1_w (half)
__device__ __align__(16) __half g_w2h [HH * HH];     // lin2_w (half)
__device__ __align__(16) __half g_xwh [NPAD * CC];   // x @ conv_w (fp16)
__device__ __align__(16) __half g_acch[NPAD * CC];   // h (fp16), padding stays 0
__device__ __align__(16) __half g_h1h [NPAD * HH];   // relu(h@W1^T+b1) (fp16)

// ---------------- graph-side kernels -----------------------------------------
__global__ void zero_cnt_kernel() {
    int i = blockIdx.x * blockDim.x + threadIdx.x;
    if (i < NN) g_cnt[i] = 0;
}

__global__ void build_adj_kernel(const int* __restrict__ ei) {
    int e = blockIdx.x * blockDim.x + threadIdx.x;
    if (e >= EE) return;
    int s = ei[e];
    int d = ei[EE + e];
    int slot = atomicAdd(&g_cnt[d], 1);
    if (slot < MAXDEG) g_adj[(long long)d * MAXDEG + slot] = s;
}

__global__ void dinv_kernel() {
    int i = blockIdx.x * blockDim.x + threadIdx.x;
    if (i < NN) g_dinv[i] = rsqrtf((float)g_cnt[i] + 1.0f);
}

// ---------------- prep: convert weights + init out ---------------------------
__global__ void prep_kernel(const float* __restrict__ cw,
                            const float* __restrict__ w1,
                            const float* __restrict__ w2,
                            const float* __restrict__ b3,
                            float* __restrict__ outp) {
    int i = blockIdx.x * blockDim.x + threadIdx.x;   // 114688
    if (i < BB) outp[i] = b3[0];
    if (i < CC * CC) {
        int k = i >> 7, n = i & 127;
        g_cwTh[n * CC + k] = __float2half_rn(cw[k * CC + n]);
    } else if (i < CC * CC + HH * CC) {
        int j = i - CC * CC;
        g_w1h[j] = __float2half_rn(w1[j]);
    } else if (i < CC * CC + HH * CC + HH * HH) {
        int j = i - CC * CC - HH * CC;
        g_w2h[j] = __float2half_rn(w2[j]);
    }
}

// ---------------- helpers ----------------------------------------------------
__device__ __forceinline__ uint32_t packh2(float a, float b) {
    __half2 h = __floats2half2_rn(a, b);
    return *(uint32_t*)&h;
}

__device__ __forceinline__ void ldsm4(uint32_t& r0, uint32_t& r1,
                                      uint32_t& r2, uint32_t& r3, uint32_t addr) {
    asm volatile("ldmatrix.sync.aligned.m8n8.x4.shared.b16 {%0,%1,%2,%3}, [%4];"
                 : "=r"(r0), "=r"(r1), "=r"(r2), "=r"(r3) : "r"(addr));
}

__device__ __forceinline__ void cpasync16(uint32_t dst, const void* src) {
    asm volatile("cp.async.cg.shared.global [%0], [%1], 16;"
                 :: "r"(dst), "l"(src) : "memory");
}

#define MMA_F16(D, AV, BV)                                                      \
    asm volatile(                                                               \
        "mma.sync.aligned.m16n8k16.row.col.f32.f16.f16.f32 "                    \
        "{%0,%1,%2,%3}, {%4,%5,%6,%7}, {%8,%9}, {%0,%1,%2,%3};"                 \
        : "+f"((D)[0]), "+f"((D)[1]), "+f"((D)[2]), "+f"((D)[3])                \
        : "r"((AV).x), "r"((AV).y), "r"((AV).z), "r"((AV).w),                   \
          "r"((BV).x), "r"((BV).y))

// ---------------- fp16 tensor-core GEMM: 3-stage cp.async + ldmatrix ---------
// C[row, n] = sum_k A[row, k] * B[n, k]   (B half, torch [n][k] layout)
// Block tile 128(M) x 128(N), KT=32 (2 ksteps of k16), 8 warps (4M x 2N).
// SMEM: row-major tiles, 32 halves (4x16B units)/row; XOR swizzle on 16B units
// pu = u ^ ((r>>1)&3): fills at 4-phase minimum, conflict-free LDSM reads.
// 3-stage pipeline: fill for tile t awaited at tile t (2 computes of slack).
// EPI 0: outh[row*CC + col] = (half)c              (conv; clamp A row reads)
// EPI 1: outh[row*HH + col] = (half)relu(c + bias[col])
// EPI 2: out0[row/20] += sum_n relu(c + bias[n]) * w3[n]   (row < arows)
template<int KDIM, int EPI, bool AHALF>
__global__ void __launch_bounds__(256, 2) hgemm_kernel(
    const void* __restrict__ Aptr,
    const __half* __restrict__ W,
    const float* __restrict__ bias,
    const float* __restrict__ w3,
    float* __restrict__ out0,
    __half* __restrict__ outh,
    int arows)
{
    __shared__ __align__(16) __half sA[3][128 * 32];   // 8 KB / stage
    __shared__ __align__(16) __half sB[3][128 * 32];   // 8 KB / stage

    const int tid = threadIdx.x;
    const int lane = tid & 31;
    const int wid = tid >> 5;
    const int wm = wid & 3;          // warp row (M)
    const int wn = wid >> 2;         // warp col (N)
    const int gid = lane >> 2;
    const int tidg = lane & 3;
    const int row0 = blockIdx.x * 128;
    const int jb = blockIdx.y * 128;

    float d[2][8][4];
#pragma unroll
    for (int i = 0; i < 2; i++)
#pragma unroll
        for (int j = 0; j < 8; j++)
#pragma unroll
            for (int r = 0; r < 4; r++) d[i][j][r] = 0.0f;

    const int laneRowA = lane & 15;
    const int laneUHA  = lane >> 4;
    const int laneRowB = (lane & 7) + ((lane >> 4) << 3);
    const int laneUHB  = (lane >> 3) & 1;

    auto fillA = [&](int st, int kt0) {
#pragma unroll
        for (int t = 0; t < 2; t++) {
            int idx = tid + t * 256;           // 512 16B units
            int r = idx >> 2, u = idx & 3;
            int grow = row0 + r;
            if (EPI == 0 && grow >= arows) grow = 0;   // clamp reads of x
            int pu = u ^ ((r >> 1) & 3);
            if (AHALF) {
                const void* src = &((const __half*)Aptr)[(long long)grow * KDIM + kt0 + u * 8];
                uint32_t dst = (uint32_t)__cvta_generic_to_shared(&sA[st][r * 32 + pu * 8]);
                cpasync16(dst, src);
            } else {
                const float* Af = (const float*)Aptr;
                const float4 v0 = *(const float4*)&Af[(long long)grow * KDIM + kt0 + u * 8];
                const float4 v1 = *(const float4*)&Af[(long long)grow * KDIM + kt0 + u * 8 + 4];
                uint4 val;
                val.x = packh2(v0.x, v0.y); val.y = packh2(v0.z, v0.w);
                val.z = packh2(v1.x, v1.y); val.w = packh2(v1.z, v1.w);
                *(uint4*)&sA[st][r * 32 + pu * 8] = val;
            }
        }
    };
    auto fillB = [&](int st, int kt0) {
#pragma unroll
        for (int t = 0; t < 2; t++) {
            int idx = tid + t * 256;
            int r = idx >> 2, u = idx & 3;
            int pu = u ^ ((r >> 1) & 3);
            const void* src = &W[(long long)(jb + r) * KDIM + kt0 + u * 8];
            uint32_t dst = (uint32_t)__cvta_generic_to_shared(&sB[st][r * 32 + pu * 8]);
            cpasync16(dst, src);
        }
    };
    auto compute = [&](int st) {
        const uint32_t baseA = (uint32_t)__cvta_generic_to_shared(&sA[st][0]);
        const uint32_t baseB = (uint32_t)__cvta_generic_to_shared(&sB[st][0]);
#pragma unroll
        for (int s = 0; s < 2; s++) {
            uint4 av[2];
            uint2 bv[8];
#pragma unroll
            for (int i = 0; i < 2; i++) {
                int row = (wm * 2 + i) * 16 + laneRowA;
                int u = s * 2 + laneUHA;
                uint32_t addr = baseA + (uint32_t)((row * 4 + (u ^ ((row >> 1) & 3))) << 4);
                ldsm4(av[i].x, av[i].y, av[i].z, av[i].w, addr);
            }
#pragma unroll
            for (int jj = 0; jj < 4; jj++) {
                int row = wn * 64 + jj * 16 + laneRowB;
                int u = s * 2 + laneUHB;
                uint32_t addr = baseB + (uint32_t)((row * 4 + (u ^ ((row >> 1) & 3))) << 4);
                ldsm4(bv[jj * 2].x, bv[jj * 2].y, bv[jj * 2 + 1].x, bv[jj * 2 + 1].y, addr);
            }
#pragma unroll
            for (int i = 0; i < 2; i++)
#pragma unroll
                for (int j = 0; j < 8; j++)
                    MMA_F16(d[i][j], av[i], bv[j]);
        }
    };

    constexpr int NT = KDIM / 32;
    fillA(0, 0);
    fillB(0, 0);
    asm volatile("cp.async.commit_group;");
    if (NT > 1) {
        fillA(1, 32);
        fillB(1, 32);
        asm volatile("cp.async.commit_group;");
    }
#pragma unroll
    for (int t = 0; t < NT; t++) {
        if (t + 2 < NT) {
            fillA((t + 2) % 3, (t + 2) * 32);
            fillB((t + 2) % 3, (t + 2) * 32);
            asm volatile("cp.async.commit_group;");
        }
        if (t + 2 < NT)      asm volatile("cp.async.wait_group 2;");
        else if (t + 1 < NT) asm volatile("cp.async.wait_group 1;");
        else                 asm volatile("cp.async.wait_group 0;");
        __syncthreads();
        compute(t % 3);
        __syncthreads();
    }

    if (EPI == 0) {
#pragma unroll
        for (int i = 0; i < 2; i++) {
            const int rbase = row0 + (wm * 2 + i) * 16 + gid;
#pragma unroll
            for (int j = 0; j < 8; j++) {
                const int c = jb + (wn * 8 + j) * 8 + tidg * 2;
                *(__half2*)&outh[(long long)rbase * CC + c] =
                    __floats2half2_rn(d[i][j][0], d[i][j][1]);
                *(__half2*)&outh[(long long)(rbase + 8) * CC + c] =
                    __floats2half2_rn(d[i][j][2], d[i][j][3]);
            }
        }
    } else if (EPI == 1) {
#pragma unroll
        for (int i = 0; i < 2; i++) {
            const int rbase = row0 + (wm * 2 + i) * 16 + gid;
#pragma unroll
            for (int j = 0; j < 8; j++) {
                const int c = jb + (wn * 8 + j) * 8 + tidg * 2;
                const float bb0 = bias[c], bb1 = bias[c + 1];
                *(__half2*)&outh[(long long)rbase * HH + c] =
                    __floats2half2_rn(fmaxf(d[i][j][0] + bb0, 0.0f),
                                      fmaxf(d[i][j][1] + bb1, 0.0f));
                *(__half2*)&outh[(long long)(rbase + 8) * HH + c] =
                    __floats2half2_rn(fmaxf(d[i][j][2] + bb0, 0.0f),
                                      fmaxf(d[i][j][3] + bb1, 0.0f));
            }
        }
    } else {
#pragma unroll
        for (int i = 0; i < 2; i++) {
            float v0 = 0.0f, v1 = 0.0f;
#pragma unroll
            for (int j = 0; j < 8; j++) {
                const int c = jb + (wn * 8 + j) * 8 + tidg * 2;
                const float bb0 = bias[c], bb1 = bias[c + 1];
                const float w30 = w3[c], w31 = w3[c + 1];
                v0 += fmaxf(d[i][j][0] + bb0, 0.0f) * w30
                    + fmaxf(d[i][j][1] + bb1, 0.0f) * w31;
                v1 += fmaxf(d[i][j][2] + bb0, 0.0f) * w30
                    + fmaxf(d[i][j][3] + bb1, 0.0f) * w31;
            }
            v0 += __shfl_xor_sync(0xffffffffu, v0, 1);
            v0 += __shfl_xor_sync(0xffffffffu, v0, 2);
            v1 += __shfl_xor_sync(0xffffffffu, v1, 1);
            v1 += __shfl_xor_sync(0xffffffffu, v1, 2);
            if (tidg == 0) {
                const int r0 = row0 + (wm * 2 + i) * 16 + gid;
                if (r0 < arows)     atomicAdd(&out0[r0 / 20], v0);
                if (r0 + 8 < arows) atomicAdd(&out0[(r0 + 8) / 20], v1);
            }
        }
    }
}

// ---------------- pull aggregation + fused conv epilogue ---------------------
__device__ __forceinline__ float4 load_xw_row(int node, int lane) {
    const uint2 u = *(const uint2*)(g_xwh + (long long)node * CC + lane * 4);
    __half2 a = *(const __half2*)&u.x;
    __half2 b = *(const __half2*)&u.y;
    float2 fa = __half22float2(a), fb = __half22float2(b);
    return make_float4(fa.x, fa.y, fb.x, fb.y);
}

__global__ void __launch_bounds__(256) aggregate_kernel(
    const float* __restrict__ x, const float* __restrict__ cb)
{
    const int wid = threadIdx.x >> 5;
    const int lane = threadIdx.x & 31;
    const int d = blockIdx.x * 8 + wid;
    if (d >= NN) return;

    int cnt = g_cnt[d];
    if (cnt > MAXDEG) cnt = MAXDEG;
    const float dv = g_dinv[d];

    const int* adj = &g_adj[(long long)d * MAXDEG];
    int s0 = (lane < cnt) ? adj[lane] : 0;
    int s1 = (lane + 32 < cnt) ? adj[lane + 32] : 0;
    float n0 = (lane < cnt) ? g_dinv[s0] * dv : 0.0f;
    float n1 = (lane + 32 < cnt) ? g_dinv[s1] * dv : 0.0f;

    float4 acc = load_xw_row(d, lane);
    const float sl = dv * dv;
    acc.x *= sl; acc.y *= sl; acc.z *= sl; acc.w *= sl;

    int i = 0;
    for (; i + 4 <= cnt; i += 4) {
#pragma unroll
        for (int u = 0; u < 4; u++) {
            int e = i + u;
            int src = __shfl_sync(0xffffffffu, (e < 32) ? s0 : s1, e & 31);
            float nm = __shfl_sync(0xffffffffu, (e < 32) ? n0 : n1, e & 31);
            float4 v = load_xw_row(src, lane);
            acc.x += v.x * nm; acc.y += v.y * nm;
            acc.z += v.z * nm; acc.w += v.w * nm;
        }
    }
    for (; i < cnt; i++) {
        int src = __shfl_sync(0xffffffffu, (i < 32) ? s0 : s1, i & 31);
        float nm = __shfl_sync(0xffffffffu, (i < 32) ? n0 : n1, i & 31);
        float4 v = load_xw_row(src, lane);
        acc.x += v.x * nm; acc.y += v.y * nm;
        acc.z += v.z * nm; acc.w += v.w * nm;
    }

    float4 bb = ((const float4*)cb)[lane];
    float4 xv = ((const float4*)(x + (long long)d * CC))[lane];
    uint2 st;
    st.x = packh2(fmaxf(acc.x + bb.x, 0.0f) + xv.x,
                  fmaxf(acc.y + bb.y, 0.0f) + xv.y);
    st.y = packh2(fmaxf(acc.z + bb.z, 0.0f) + xv.z,
                  fmaxf(acc.w + bb.w, 0.0f) + xv.w);
    *(uint2*)(g_acch + (long long)d * CC + lane * 4) = st;
}

// ---------------- launch -----------------------------------------------------
extern "C" void kernel_launch(void* const* d_in, const int* in_sizes, int n_in,
                              void* d_out, int out_size) {
    const float* x   = (const float*)d_in[0];
    const int*   ei  = (const int*)d_in[1];
    const float* cw  = (const float*)d_in[2];
    const float* cb  = (const float*)d_in[3];
    const float* w1  = (const float*)d_in[4];
    const float* b1  = (const float*)d_in[5];
    const float* w2  = (const float*)d_in[6];
    const float* b2  = (const float*)d_in[7];
    const float* w3  = (const float*)d_in[8];
    const float* b3  = (const float*)d_in[9];
    float* outp = (float*)d_out;

    __half* p_cwTh; cudaGetSymbolAddress((void**)&p_cwTh, g_cwTh);
    __half* p_w1h;  cudaGetSymbolAddress((void**)&p_w1h,  g_w1h);
    __half* p_w2h;  cudaGetSymbolAddress((void**)&p_w2h,  g_w2h);
    __half* p_xwh;  cudaGetSymbolAddress((void**)&p_xwh,  g_xwh);
    __half* p_acch; cudaGetSymbolAddress((void**)&p_acch, g_acch);
    __half* p_h1h;  cudaGetSymbolAddress((void**)&p_h1h,  g_h1h);

    // one-time host resources (created on the uncaptured correctness call)
    static cudaStream_t s_side = nullptr;
    static cudaEvent_t evFork = nullptr, evJoin = nullptr;
    if (!s_side) {
        cudaStreamCreateWithFlags(&s_side, cudaStreamNonBlocking);
        cudaEventCreateWithFlags(&evFork, cudaEventDisableTiming);
        cudaEventCreateWithFlags(&evJoin, cudaEventDisableTiming);
    }

    // fork: side stream runs prep + conv GEMM while main stream builds the graph
    cudaEventRecord(evFork, 0);
    cudaStreamWaitEvent(s_side, evFork, 0);

    prep_kernel<<<(CC * CC + HH * CC + HH * HH + 255) / 256, 256, 0, s_side>>>(
        cw, w1, w2, b3, outp);
    hgemm_kernel<128, 0, false><<<dim3(NPAD / 128, 1), 256, 0, s_side>>>(
        x, p_cwTh, nullptr, nullptr, nullptr, p_xwh, NN);
    cudaEventRecord(evJoin, s_side);

    zero_cnt_kernel<<<(NN + 255) / 256, 256>>>();
    build_adj_kernel<<<(EE + 255) / 256, 256>>>(ei);
    dinv_kernel<<<(NN + 255) / 256, 256>>>();

    // join: aggregation needs g_xwh (side) + g_cnt/g_dinv (main)
    cudaStreamWaitEvent(0, evJoin, 0);

    aggregate_kernel<<<(NN + 7) / 8, 256>>>(x, cb);

    // mlp1: g_h1h = relu(h @ W1^T + b1)
    hgemm_kernel<128, 1, true><<<dim3(NPAD / 128, 2), 256>>>(
        p_acch, p_w1h, b1, nullptr, nullptr, p_h1h, NN);

    // mlp2 + fused sum/lin3
    hgemm_kernel<256, 2, true><<<dim3(NPAD / 128, 2), 256>>>(
        p_h1h, p_w2h, b2, w3, outp, nullptr, NN);
}